// round 10
// baseline (speedup 1.0000x reference)
#include <cuda_runtime.h>

// Problem shape (fixed by the dataset)
#define TT 4096
#define NB 16
#define CC 512
#define NC (NB * CC)            // 8192 columns
#define NC4 (NC / 4)            // 2048 float4 columns
#define TOTAL (TT * NC)         // 33,554,432 floats for new_x

#define NSEG 4
#define SEG_T (TT / NSEG)       // 1024 rows/segment = 32 MB (L2-resident)
#define CHUNK 16                // rows per thread
#define CPS (SEG_T / CHUNK)     // 64 chunks per segment
#define NCH (TT / CHUNK)        // 256 chunks total
#define ROLE_BLOCKS ((CPS * NC4) / 256)   // 512 blocks for sum/scanOut roles
#define CARRY_BLOCKS (NC4 / 256)          // 8 blocks
#define RCP_BLOCKS ((TT * NB) / 256)      // 256

// Static scratch (no allocations; fully rewritten every replay — graph-safe)
__device__ float4 g_agg[NCH * NC4];     // 8 MB: per-(chunk, col4) sums (L2-hot)
__device__ float4 g_carry[2][NC4];      // 64 KB: double-buffered segment carries
__device__ float  g_rcp[TT * NB];       // 256 KB: 1/(t+1+len_n), [t][n]

__device__ __forceinline__ float4 f4add(float4 a, float4 b) {
    return make_float4(a.x + b.x, a.y + b.y, a.z + b.z, a.w + b.w);
}

// Sum role: per-(chunk, col4) partial sums. __ldcg: bypass L1, fill L2 so the
// scanOut role in the NEXT launch re-reads as L2 hits.
__device__ __forceinline__ void sum_role(const float4* __restrict__ x4,
                                         int idx, int seg) {
    int nc4 = idx & (NC4 - 1);
    int gc = seg * CPS + (idx >> 11);
    const float4* p = x4 + (size_t)gc * CHUNK * NC4 + nc4;
    float4 s = make_float4(0.f, 0.f, 0.f, 0.f);
#pragma unroll
    for (int i = 0; i < CHUNK; i++) s = f4add(s, __ldcg(p + (size_t)i * NC4));
    g_agg[gc * NC4 + nc4] = s;
}

// Carry role: carry(s+1) = carry(s) + column-sum of segment s's aggregates.
// 2048 threads, 64 independent L2 loads each.
__device__ __forceinline__ void carry_role(int col4, int s) {
    float4 c = g_carry[s & 1][col4];
    const float4* pa = &g_agg[s * CPS * NC4 + col4];
#pragma unroll 8
    for (int j = 0; j < CPS; j++) c = f4add(c, pa[(size_t)j * NC4]);
    g_carry[(s + 1) & 1][col4] = c;
}

// kA: sum(seg 0) + reciprocal table + carry(0) = cached seed.
__global__ void __launch_bounds__(256)
kA(const float4* __restrict__ x4, const int* __restrict__ cached_len,
   const float4* __restrict__ avg4) {
    int bid = blockIdx.x, tid = threadIdx.x;
    if (bid < ROLE_BLOCKS) {
        sum_role(x4, bid * 256 + tid, 0);
    } else if (bid < ROLE_BLOCKS + RCP_BLOCKS) {
        int idx = (bid - ROLE_BLOCKS) * 256 + tid;     // 0 .. TT*NB-1
        int n = idx & (NB - 1);
        int t = idx >> 4;
        g_rcp[idx] = 1.0f / ((float)(t + 1) + (float)cached_len[n]);
    } else {
        int col4 = (bid - ROLE_BLOCKS - RCP_BLOCKS) * 256 + tid;
        float lenf = (float)cached_len[col4 >> 7];
        float4 a = avg4[col4];
        g_carry[0][col4] = make_float4(a.x * lenf, a.y * lenf, a.z * lenf, a.w * lenf);
    }
}

// kFused(s): [0,b_sum): sum(s+1) | [b_sum,b_carry): carryUpd(s) | rest: scanOut(s).
// scanOut computes its own base: carry(s) + fold of predecessor chunk aggs
// (block-uniform loop bound, coalesced L2-resident loads). No kscan, no g_base.
__global__ void __launch_bounds__(256)
kFused(const float4* __restrict__ x4, const int* __restrict__ cached_len,
       float4* __restrict__ out4, int s, int b_sum, int b_carry, int extras) {
    int bid = blockIdx.x, tid = threadIdx.x;

    if (bid < b_sum) {                                   // DRAM stream: seg s+1
        sum_role(x4, bid * 256 + tid, s + 1);
        return;
    }
    if (bid < b_carry) {                                 // tiny: carry(s+1)
        carry_role((bid - b_sum) * 256 + tid, s);
        return;
    }

    // scanOut role: segment s (x[s] L2-hot from previous launch).
    int idx = (bid - b_carry) * 256 + tid;
    int nc4 = idx & (NC4 - 1);
    int j = idx >> 11;                                   // chunk within segment, block-uniform
    int gc = s * CPS + j;
    int n = nc4 >> 7;                                    // warp-uniform

    // Base: carry + predecessor aggregates of this segment (avg 32 indep loads).
    float4 run = g_carry[s & 1][nc4];
    const float4* pa = &g_agg[s * CPS * NC4 + nc4];
#pragma unroll 8
    for (int ch = 0; ch < j; ch++) run = f4add(run, pa[(size_t)ch * NC4]);

    const float4* px = x4   + (size_t)gc * CHUNK * NC4 + nc4;
    float4*       po = out4 + (size_t)gc * CHUNK * NC4 + nc4;
    const float*  pr = g_rcp + (size_t)gc * CHUNK * NB + n;

    float4 last = make_float4(0.f, 0.f, 0.f, 0.f);
#pragma unroll
    for (int i = 0; i < CHUNK; i++) {
        float4 v = __ldcs(px + (size_t)i * NC4);         // hit-then-evict (dead after this)
        run = f4add(run, v);
        float r = pr[(size_t)i * NB];
        last.x = run.x * r; last.y = run.y * r;
        last.z = run.z * r; last.w = run.w * r;
        __stcs(po + (size_t)i * NC4, last);              // evict-first store
    }

    if (extras && s == NSEG - 1) {
        // Tuple order: [new_x | new_cached_len (as float) | new_cached_avg]
        if (j == CPS - 1)
            out4[(TOTAL + NB) / 4 + nc4] = last;         // new_x[T-1]
        if (idx < NB) {
            float* outf = (float*)out4;
            outf[TOTAL + idx] = (float)(cached_len[idx] + TT);
        }
    }
}

extern "C" void kernel_launch(void* const* d_in, const int* in_sizes, int n_in,
                              void* d_out, int out_size) {
    const float4* x4         = (const float4*)d_in[0];   // (T, N, C)
    const int*    cached_len = (const int*)d_in[1];      // (N,)
    const float4* avg4       = (const float4*)d_in[2];   // (N, C)
    float4* out4 = (float4*)d_out;

    int extras = (out_size >= TOTAL + NB + NC) ? 1 : 0;

    kA<<<ROLE_BLOCKS + RCP_BLOCKS + CARRY_BLOCKS, 256>>>(x4, cached_len, avg4);
    for (int s = 0; s < NSEG; s++) {
        int nb_sum   = (s + 1 < NSEG) ? ROLE_BLOCKS : 0;
        int nb_carry = (s + 1 < NSEG) ? CARRY_BLOCKS : 0;
        int b_carry = nb_sum + nb_carry;
        kFused<<<b_carry + ROLE_BLOCKS, 256>>>(x4, cached_len, out4,
                                               s, nb_sum, b_carry, extras);
    }
}

// round 11
// speedup vs baseline: 1.0712x; 1.0712x over previous
#include <cuda_runtime.h>

// Problem shape (fixed by the dataset)
#define TT 4096
#define NB 16
#define CC 512
#define NC (NB * CC)            // 8192 columns
#define NC4 (NC / 4)            // 2048 float4 columns
#define TOTAL (TT * NC)         // 33,554,432 floats for new_x

#define NSEG 4
#define SEG_T (TT / NSEG)       // 1024 rows/segment = 32 MB (L2-resident)
#define CHUNK 16                // rows per thread
#define CPS (SEG_T / CHUNK)     // 64 chunks per segment
#define NCH (TT / CHUNK)        // 256 chunks total
#define ROLE_BLOCKS ((CPS * NC4) / 256)   // 512 blocks for sum/scanOut roles
#define KSCAN_BLOCKS ((NC4 * 32) / 256)   // 256 blocks (warp per col4)
#define RCP_BLOCKS ((TT * NB) / 256)      // 256

// Static scratch (no allocations; fully rewritten every replay — graph-safe)
__device__ float4 g_agg[NCH * NC4];    // 8 MB: per-(chunk, col4) sums
__device__ float4 g_base[NCH * NC4];   // 8 MB: exclusive bases (seeded)
__device__ float4 g_carry[NC4];        // 32 KB: carry across segments
__device__ float  g_rcp[TT * NB];      // 256 KB: 1/(t+1+len_n), [t][n]
__device__ int    g_ctr[NSEG];         // per-segment "bases ready" counters

__device__ __forceinline__ float4 f4add(float4 a, float4 b) {
    return make_float4(a.x + b.x, a.y + b.y, a.z + b.z, a.w + b.w);
}
__device__ __forceinline__ float4 f4shfl_up(float4 v, int off) {
    v.x = __shfl_up_sync(0xffffffffu, v.x, off);
    v.y = __shfl_up_sync(0xffffffffu, v.y, off);
    v.z = __shfl_up_sync(0xffffffffu, v.z, off);
    v.w = __shfl_up_sync(0xffffffffu, v.w, off);
    return v;
}

// Sum role: per-(chunk, col4) partial sums. __ldcg: bypass L1, fill L2 so the
// NEXT launch's scanOut re-reads this segment as L2 hits.
__device__ __forceinline__ void sum_role(const float4* __restrict__ x4,
                                         int idx, int seg) {
    int nc4 = idx & (NC4 - 1);
    int gc = seg * CPS + (idx >> 11);
    const float4* p = x4 + (size_t)gc * CHUNK * NC4 + nc4;
    float4 s = make_float4(0.f, 0.f, 0.f, 0.f);
#pragma unroll
    for (int i = 0; i < CHUNK; i++) s = f4add(s, __ldcg(p + (size_t)i * NC4));
    g_agg[gc * NC4 + nc4] = s;
}

// kA: sum(seg 0) + reciprocal table + zero handoff counters.
__global__ void __launch_bounds__(256)
kA(const float4* __restrict__ x4, const int* __restrict__ cached_len) {
    int bid = blockIdx.x, tid = threadIdx.x;
    if (bid < ROLE_BLOCKS) {
        sum_role(x4, bid * 256 + tid, 0);
    } else {
        if (bid == ROLE_BLOCKS && tid < NSEG) g_ctr[tid] = 0;
        int idx = (bid - ROLE_BLOCKS) * 256 + tid;     // 0 .. TT*NB-1
        int n = idx & (NB - 1);
        int t = idx >> 4;
        g_rcp[idx] = 1.0f / ((float)(t + 1) + (float)cached_len[n]);
    }
}

// kFused(s): [0,256): kscan(s) | [256,768): scanOut(s) | [768,...): sum(s+1).
__global__ void __launch_bounds__(256)
kFused(const float4* __restrict__ x4, const int* __restrict__ cached_len,
       const float4* __restrict__ avg4, float4* __restrict__ out4,
       int s, int extras) {
    int bid = blockIdx.x, tid = threadIdx.x;

    if (bid < KSCAN_BLOCKS) {
        // ── kscan(s): warp-per-col4 shfl scan of seg s's 64 chunk aggregates ──
        int widx = bid * 256 + tid;
        int col4 = widx >> 5;                  // 0 .. NC4-1
        int lane = widx & 31;

        float4 carry;
        if (s == 0) {
            float lenf = (float)cached_len[col4 >> 7];
            float4 a = avg4[col4];
            carry = make_float4(a.x * lenf, a.y * lenf, a.z * lenf, a.w * lenf);
        } else {
            carry = g_carry[col4];
        }

        int gc0 = s * CPS;
        float4 a0 = g_agg[(gc0 + 2 * lane)     * NC4 + col4];
        float4 a1 = g_agg[(gc0 + 2 * lane + 1) * NC4 + col4];
        float4 incl = f4add(a0, a1);
#pragma unroll
        for (int off = 1; off < 32; off <<= 1) {
            float4 up = f4shfl_up(incl, off);
            if (lane >= off) incl = f4add(incl, up);
        }
        float4 excl = f4shfl_up(incl, 1);
        if (lane == 0) excl = make_float4(0.f, 0.f, 0.f, 0.f);

        float4 b0 = f4add(carry, excl);
        g_base[(gc0 + 2 * lane)     * NC4 + col4] = b0;
        g_base[(gc0 + 2 * lane + 1) * NC4 + col4] = f4add(b0, a0);
        if (lane == 31) g_carry[col4] = f4add(carry, incl);

        // Publish: stores → fence (release) → counter bump.
        __threadfence();
        __syncthreads();
        if (tid == 0) atomicAdd(&g_ctr[s], 1);
        return;
    }

    if (bid >= KSCAN_BLOCKS + ROLE_BLOCKS) {             // sum role: seg s+1
        sum_role(x4, (bid - KSCAN_BLOCKS - ROLE_BLOCKS) * 256 + tid, s + 1);
        return;
    }

    // ── scanOut(s): wait for in-launch kscan handoff, then stream ──
    if (tid == 0) {
        volatile int* c = &g_ctr[s];
        while (*c != KSCAN_BLOCKS) __nanosleep(32);
    }
    __syncthreads();
    __threadfence();                                     // acquire

    int idx = (bid - KSCAN_BLOCKS) * 256 + tid;
    int nc4 = idx & (NC4 - 1);
    int j = idx >> 11;                                   // block-uniform chunk
    int gc = s * CPS + j;
    int n = nc4 >> 7;                                    // warp-uniform

    float4 run = __ldcg(&g_base[gc * NC4 + nc4]);
    const float4* px = x4   + (size_t)gc * CHUNK * NC4 + nc4;
    float4*       po = out4 + (size_t)gc * CHUNK * NC4 + nc4;
    const float*  pr = g_rcp + (size_t)gc * CHUNK * NB + n;

    float4 last = make_float4(0.f, 0.f, 0.f, 0.f);
#pragma unroll
    for (int i = 0; i < CHUNK; i++) {
        float4 v = __ldcs(px + (size_t)i * NC4);         // hit-then-evict (dead data)
        run = f4add(run, v);
        float r = pr[(size_t)i * NB];
        last.x = run.x * r; last.y = run.y * r;
        last.z = run.z * r; last.w = run.w * r;
        __stcs(po + (size_t)i * NC4, last);              // evict-first store
    }

    if (extras && s == NSEG - 1) {
        // Tuple order: [new_x | new_cached_len (as float) | new_cached_avg]
        if (j == CPS - 1)
            out4[(TOTAL + NB) / 4 + nc4] = last;         // new_x[T-1]
        if (idx < NB) {
            float* outf = (float*)out4;
            outf[TOTAL + idx] = (float)(cached_len[idx] + TT);
        }
    }
}

extern "C" void kernel_launch(void* const* d_in, const int* in_sizes, int n_in,
                              void* d_out, int out_size) {
    const float4* x4         = (const float4*)d_in[0];   // (T, N, C)
    const int*    cached_len = (const int*)d_in[1];      // (N,)
    const float4* avg4       = (const float4*)d_in[2];   // (N, C)
    float4* out4 = (float4*)d_out;

    int extras = (out_size >= TOTAL + NB + NC) ? 1 : 0;

    kA<<<ROLE_BLOCKS + RCP_BLOCKS, 256>>>(x4, cached_len);
    for (int s = 0; s < NSEG; s++) {
        int nb_sum = (s + 1 < NSEG) ? ROLE_BLOCKS : 0;
        kFused<<<KSCAN_BLOCKS + ROLE_BLOCKS + nb_sum, 256>>>(
            x4, cached_len, avg4, out4, s, extras);
    }
}